// round 16
// baseline (speedup 1.0000x reference)
#include <cuda_runtime.h>
#include <cuda_bf16.h>
#include <cuda_fp16.h>
#include <cstdint>

// Problem constants
#define NB   8
#define SEQ  1024
#define EMB  768
#define NH   12
#define HD   64
#define BH   (NB*NH)          // 96
#define NTOK (BH*SEQ*HD)      // 6291456
#define EXP_OFF 8.0f
#define EXP_CAP 11.0f         // exp arg clamp: keeps P < 60000 in fp16

// ---------------- fp16 split helpers ---------------------------------------
__device__ __forceinline__ void split2h(float2 f, uint32_t& hw, uint32_t& lw) {
    __half2 h = __float22half2_rn(f);
    float2 hf = __half22float2(h);
    __half2 l = __float22half2_rn(make_float2(f.x - hf.x, f.y - hf.y));
    hw = *(uint32_t*)&h;
    lw = *(uint32_t*)&l;
}

// ---------------- scratch (static device arrays; no allocation) -------------
__device__ __half g_xh[NTOK], g_xl[NTOK];          // LN'd x, fp16 hi/lo
__device__ __half g_qh[NTOK];                      // q,k,v: fp16 (hi) only
__device__ __half g_kh[NTOK];
__device__ __half g_vh[NTOK];
__device__ __half g_wqh[HD*HD], g_wql[HD*HD];      // W splits [n][e]
__device__ __half g_wkh[HD*HD], g_wkl[HD*HD];
__device__ __half g_wvh[HD*HD], g_wvl[HD*HD];

// ==================== Kernel 0: split weights to fp16 hi/lo =================
__global__ void w_split_kernel(const float* __restrict__ Wq,
                               const float* __restrict__ Wk,
                               const float* __restrict__ Wv)
{
    int i = blockIdx.x*256 + threadIdx.x;
    if (i < HD*HD) {
        float q = Wq[i], k = Wk[i], v = Wv[i];
        __half qh = __float2half_rn(q);
        __half kh = __float2half_rn(k);
        __half vh = __float2half_rn(v);
        g_wqh[i] = qh; g_wql[i] = __float2half_rn(q - __half2float(qh));
        g_wkh[i] = kh; g_wkl[i] = __float2half_rn(k - __half2float(kh));
        g_wvh[i] = vh; g_wvl[i] = __float2half_rn(v - __half2float(vh));
    }
}

// ==================== Kernel 1a: LayerNorm + fp16 hi/lo split ===============
__global__ void __launch_bounds__(256)
ln_split_kernel(const float* __restrict__ x,
                const float* __restrict__ ln_w, const float* __restrict__ ln_b)
{
    const int wid  = threadIdx.x >> 5;
    const int lane = threadIdx.x & 31;
    const int row  = blockIdx.x*8 + wid;
    const int cb   = lane*24;

    float v[24];
    #pragma unroll
    for (int i = 0; i < 6; i++)
        *(float4*)&v[i*4] = *(const float4*)&x[(size_t)row*EMB + cb + i*4];

    float s = 0.f, s2 = 0.f;
    #pragma unroll
    for (int i = 0; i < 24; i++) { s += v[i]; s2 += v[i]*v[i]; }
    #pragma unroll
    for (int m = 16; m; m >>= 1) {
        s  += __shfl_xor_sync(0xffffffffu, s,  m);
        s2 += __shfl_xor_sync(0xffffffffu, s2, m);
    }
    const float mu = s * (1.f/EMB);
    const float rs = rsqrtf(fmaf(-mu, mu, s2 * (1.f/EMB)) + 1e-5f);

    float wv[24], bv[24];
    #pragma unroll
    for (int i = 0; i < 6; i++) {
        *(float4*)&wv[i*4] = *(const float4*)&ln_w[cb + i*4];
        *(float4*)&bv[i*4] = *(const float4*)&ln_b[cb + i*4];
    }

    uint32_t hw[12], lw[12];
    #pragma unroll
    for (int p = 0; p < 12; p++) {
        float a = (v[2*p]   - mu)*rs*wv[2*p]   + bv[2*p];
        float b = (v[2*p+1] - mu)*rs*wv[2*p+1] + bv[2*p+1];
        split2h(make_float2(a, b), hw[p], lw[p]);
    }
    const size_t ob = ((size_t)row*EMB + cb)*2;
    #pragma unroll
    for (int i = 0; i < 3; i++) {
        *(uint4*)((char*)g_xh + ob + i*16) = *(uint4*)&hw[i*4];
        *(uint4*)((char*)g_xl + ob + i*16) = *(uint4*)&lw[i*4];
    }
}

// ==================== Kernel 1b: QKV projection via HMMA fp16x3 =============
__device__ __forceinline__ uint32_t smem_u32(const void* p) {
    uint32_t a;
    asm("{ .reg .u64 t; cvta.to.shared.u64 t, %1; cvt.u32.u64 %0, t; }"
        : "=r"(a) : "l"(p));
    return a;
}
__device__ __forceinline__ void ldsm4(uint32_t& r0, uint32_t& r1,
                                      uint32_t& r2, uint32_t& r3, uint32_t a) {
    asm volatile("ldmatrix.sync.aligned.m8n8.x4.shared.b16 {%0,%1,%2,%3}, [%4];"
                 : "=r"(r0), "=r"(r1), "=r"(r2), "=r"(r3) : "r"(a));
}
__device__ __forceinline__ void ldsm4t(uint32_t& r0, uint32_t& r1,
                                       uint32_t& r2, uint32_t& r3, uint32_t a) {
    asm volatile("ldmatrix.sync.aligned.m8n8.x4.trans.shared.b16 {%0,%1,%2,%3}, [%4];"
                 : "=r"(r0), "=r"(r1), "=r"(r2), "=r"(r3) : "r"(a));
}
__device__ __forceinline__ void mma_f16(float* c, const uint32_t* a,
                                        uint32_t b0, uint32_t b1) {
    asm volatile(
        "mma.sync.aligned.m16n8k16.row.col.f32.f16.f16.f32 "
        "{%0,%1,%2,%3}, {%4,%5,%6,%7}, {%8,%9}, {%0,%1,%2,%3};"
        : "+f"(c[0]), "+f"(c[1]), "+f"(c[2]), "+f"(c[3])
        : "r"(a[0]), "r"(a[1]), "r"(a[2]), "r"(a[3]), "r"(b0), "r"(b1));
}
__device__ __forceinline__ void cp16(uint32_t saddr, const void* g) {
    asm volatile("cp.async.cg.shared.global [%0], [%1], 16;"
                 :: "r"(saddr), "l"(g));
}
__device__ __forceinline__ uint32_t f16x2(float a, float b) {
    __half2 h = __float22half2_rn(make_float2(a, b));
    return *(uint32_t*)&h;
}

#define QXH 0
#define QXL 16384
#define QW  32768
#define QKV_SMEM 81920

__global__ void __launch_bounds__(256, 2)
qkv_mma_kernel(const float* __restrict__ bq, const float* __restrict__ bk,
               const float* __restrict__ bv)
{
    extern __shared__ char smem[];
    const uint32_t sb = smem_u32(smem);
    const int tid  = threadIdx.x;
    const int w    = tid >> 5;
    const int lane = tid & 31;
    const int m0   = blockIdx.x*128;

    for (int i = tid; i < 1024; i += 256) {
        int row = i >> 3, seg = i & 7;
        uint32_t off = (uint32_t)row*128 + (((uint32_t)seg*16) ^ (((uint32_t)row & 7) << 4));
        size_t gb = (size_t)(m0 + row)*128 + seg*16;
        cp16(sb + QXH + off, (const char*)g_xh + gb);
        cp16(sb + QXL + off, (const char*)g_xl + gb);
    }
    for (int i = tid; i < 512; i += 256) {
        int row = i >> 3, seg = i & 7;
        uint32_t off = (uint32_t)row*128 + (((uint32_t)seg*16) ^ (((uint32_t)row & 7) << 4));
        size_t gb = (size_t)row*128 + seg*16;
        cp16(sb + QW           + off, (const char*)g_wqh + gb);
        cp16(sb + QW + 8192    + off, (const char*)g_wql + gb);
        cp16(sb + QW + 16384   + off, (const char*)g_wkh + gb);
        cp16(sb + QW + 24576   + off, (const char*)g_wkl + gb);
        cp16(sb + QW + 32768   + off, (const char*)g_wvh + gb);
        cp16(sb + QW + 40960   + off, (const char*)g_wvl + gb);
    }
    asm volatile("cp.async.commit_group;" ::: "memory");
    asm volatile("cp.async.wait_group 0;" ::: "memory");
    __syncthreads();

    const int arow = 16*w + (lane & 7) + ((lane >> 3) & 1)*8;
    const uint32_t axor = ((uint32_t)arow & 7) << 4;
    const uint32_t abase = (uint32_t)arow*128;
    const uint32_t acol0 = ((uint32_t)(lane >> 4))*16;
    const int krow_l = (lane & 7) + ((lane >> 4) & 1)*8;
    const uint32_t kxor = ((uint32_t)lane & 7) << 4;
    const uint32_t kcol0 = ((uint32_t)((lane >> 3) & 1))*16;

    uint32_t XH[4][4], XL[4][4];
    #pragma unroll
    for (int kc = 0; kc < 4; kc++) {
        uint32_t a = sb + QXH + abase + (((uint32_t)kc*32 + acol0) ^ axor);
        ldsm4(XH[kc][0], XH[kc][1], XH[kc][2], XH[kc][3], a);
        uint32_t b = sb + QXL + abase + (((uint32_t)kc*32 + acol0) ^ axor);
        ldsm4(XL[kc][0], XL[kc][1], XL[kc][2], XL[kc][3], b);
    }

    const float* bias[3] = {bq, bk, bv};
    __half* outh[3] = {g_qh, g_kh, g_vh};

    const int g  = lane >> 2;
    const int t2 = (lane & 3)*2;
    const int r0 = m0 + 16*w + g;

    #pragma unroll
    for (int wt = 0; wt < 3; wt++) {
        const uint32_t wbh = sb + QW + (uint32_t)wt*16384;
        const uint32_t wbl = wbh + 8192;

        float C[8][4];
        #pragma unroll
        for (int n = 0; n < 8; n++)
            #pragma unroll
            for (int i = 0; i < 4; i++) C[n][i] = 0.f;

        #pragma unroll
        for (int np = 0; np < 4; np++) {
            const uint32_t roff = (uint32_t)(np*16 + krow_l)*128;
            #pragma unroll
            for (int kc = 0; kc < 4; kc++) {
                const uint32_t coff = ((uint32_t)kc*32 + kcol0) ^ kxor;
                uint32_t h0, h1, h2, h3, l0, l1, l2, l3;
                ldsm4(h0, h1, h2, h3, wbh + roff + coff);
                ldsm4(l0, l1, l2, l3, wbl + roff + coff);
                mma_f16(C[2*np],   XH[kc], h0, h1);
                mma_f16(C[2*np],   XH[kc], l0, l1);
                mma_f16(C[2*np],   XL[kc], h0, h1);
                mma_f16(C[2*np+1], XH[kc], h2, h3);
                mma_f16(C[2*np+1], XH[kc], l2, l3);
                mma_f16(C[2*np+1], XL[kc], h2, h3);
            }
        }

        // epilogue: +bias (fp32), round to fp16, store
        #pragma unroll
        for (int nt = 0; nt < 8; nt++) {
            const int col = nt*8 + t2;
            const float2 bb = *(const float2*)&bias[wt][col];
            uint32_t p0 = f16x2(C[nt][0] + bb.x, C[nt][1] + bb.y);
            uint32_t p1 = f16x2(C[nt][2] + bb.x, C[nt][3] + bb.y);
            *(uint32_t*)((char*)outh[wt] + ((size_t)r0*64 + col)*2)     = p0;
            *(uint32_t*)((char*)outh[wt] + ((size_t)(r0+8)*64 + col)*2) = p1;
        }
    }
}

// =============== Kernel 2: warp-MMA (HMMA fp16) flash attention =============
// 256-row q-tile, M=32 per warp (two 16-row A-tiles): each K/V ldsm feeds
// 2x the MMAs (B-fragment reuse), halving L1/ldsm pressure. 1 CTA/SM.
// S = fp16(q)·fp16(k); P = exp(clamp(S-8,<=11)) fp16; O += PH·VH.
__device__ __forceinline__ float expc(float s) {
    return __expf(fminf(s - EXP_OFF, EXP_CAP));
}

#define AQH 0
#define ASTG 32768
#define STG_SZ 32768        // KH(16K) + VH(16K) per 128-key stage
#define AT_SMEM 98304

__global__ void __launch_bounds__(256, 1)
attn_mma_kernel(float* __restrict__ out)
{
    extern __shared__ char smem[];
    const uint32_t sb = smem_u32(smem);
    const int tid  = threadIdx.x;
    const int w    = tid >> 5;
    const int lane = tid & 31;
    const int bh   = blockIdx.y;
    const int qrow0 = bh*SEQ + blockIdx.x*256;
    const int krowb = bh*SEQ;

    // ---- stage Q (256 rows) ----
    for (int i = tid; i < 2048; i += 256) {
        int row = i >> 3, seg = i & 7;
        uint32_t off = (uint32_t)row*128 + (((uint32_t)seg*16) ^ (((uint32_t)row & 7) << 4));
        *(uint4*)(smem + AQH + off) = *(const uint4*)((const char*)g_qh + (size_t)(qrow0 + row)*128 + seg*16);
    }

    // ---- prologue prefetch: k-tile 0 (128 keys: KH+VH) into stage 0 ----
    {
        const uint32_t base = sb + ASTG;
        for (int i = tid; i < 1024; i += 256) {
            int row = i >> 3, seg = i & 7;
            uint32_t off = (uint32_t)row*128 + (((uint32_t)seg*16) ^ (((uint32_t)row & 7) << 4));
            size_t gb = (size_t)(krowb + row)*128 + seg*16;
            cp16(base + off,         (const char*)g_kh + gb);
            cp16(base + 16384 + off, (const char*)g_vh + gb);
        }
        asm volatile("cp.async.commit_group;" ::: "memory");
    }
    __syncthreads();

    // lane address components
    const int arow_l = (lane & 7) + ((lane >> 3) & 1)*8;     // within 16-row tile
    const uint32_t acol0 = ((uint32_t)(lane >> 4))*16;
    const int krow_l = (lane & 7) + ((lane >> 4) & 1)*8;
    const uint32_t kxor = ((uint32_t)lane & 7) << 4;
    const uint32_t kcol0 = ((uint32_t)((lane >> 3) & 1))*16;
    const int vrow_l = (lane & 7) + ((lane >> 3) & 1)*8;
    const uint32_t vcol0 = ((uint32_t)((lane >> 4) & 1))*16;

    // resident Q fragments: 2 row-tiles x 4 kchunks
    uint32_t QH[2][4][4];
    #pragma unroll
    for (int rt = 0; rt < 2; rt++) {
        const int arow = 32*w + rt*16 + arow_l;
        const uint32_t axor = ((uint32_t)arow & 7) << 4;
        const uint32_t abase = (uint32_t)arow*128;
        #pragma unroll
        for (int kc = 0; kc < 4; kc++) {
            uint32_t a = sb + AQH + abase + (((uint32_t)kc*32 + acol0) ^ axor);
            ldsm4(QH[rt][kc][0], QH[rt][kc][1], QH[rt][kc][2], QH[rt][kc][3], a);
        }
    }

    float O[2][8][4];
    #pragma unroll
    for (int rt = 0; rt < 2; rt++)
        #pragma unroll
        for (int n = 0; n < 8; n++)
            #pragma unroll
            for (int i = 0; i < 4; i++) O[rt][n][i] = 0.f;
    float lsum[2][2];
    lsum[0][0] = lsum[0][1] = lsum[1][0] = lsum[1][1] = 0.f;

    for (int kt = 0; kt < 8; kt++) {
        const uint32_t cbase = sb + ASTG + (uint32_t)(kt & 1)*STG_SZ;

        asm volatile("cp.async.wait_group 0;" ::: "memory");
        __syncthreads();   // stage kt visible; all warps done with other stage

        if (kt + 1 < 8) {
            const int krow0 = krowb + (kt + 1)*128;
            const uint32_t pbase = sb + ASTG + (uint32_t)((kt + 1) & 1)*STG_SZ;
            for (int i = tid; i < 1024; i += 256) {
                int row = i >> 3, seg = i & 7;
                uint32_t off = (uint32_t)row*128 + (((uint32_t)seg*16) ^ (((uint32_t)row & 7) << 4));
                size_t gb = (size_t)(krow0 + row)*128 + seg*16;
                cp16(pbase + off,         (const char*)g_kh + gb);
                cp16(pbase + 16384 + off, (const char*)g_vh + gb);
            }
            asm volatile("cp.async.commit_group;" ::: "memory");
        }

        // ---- per-strip pipeline: S(np) -> exp -> PV(np), 8 strips of 16 keys
        #pragma unroll
        for (int np = 0; np < 8; np++) {
            float SH[2][2][4];
            #pragma unroll
            for (int rt = 0; rt < 2; rt++)
                #pragma unroll
                for (int n = 0; n < 2; n++)
                    #pragma unroll
                    for (int i = 0; i < 4; i++) SH[rt][n][i] = 0.f;

            const uint32_t kroff = (uint32_t)(np*16 + krow_l)*128;
            #pragma unroll
            for (int kc = 0; kc < 4; kc++) {
                const uint32_t coff = ((uint32_t)kc*32 + kcol0) ^ kxor;
                uint32_t bh0, bh1, bh2, bh3;
                ldsm4(bh0, bh1, bh2, bh3, cbase + kroff + coff);
                #pragma unroll
                for (int rt = 0; rt < 2; rt++) {
                    mma_f16(SH[rt][0], QH[rt][kc], bh0, bh1);
                    mma_f16(SH[rt][1], QH[rt][kc], bh2, bh3);
                }
            }

            uint32_t PH[2][4];
            #pragma unroll
            for (int rt = 0; rt < 2; rt++) {
                float e00 = expc(SH[rt][0][0]);
                float e01 = expc(SH[rt][0][1]);
                float e02 = expc(SH[rt][0][2]);
                float e03 = expc(SH[rt][0][3]);
                float e10 = expc(SH[rt][1][0]);
                float e11 = expc(SH[rt][1][1]);
                float e12 = expc(SH[rt][1][2]);
                float e13 = expc(SH[rt][1][3]);
                lsum[rt][0] += (e00 + e01) + (e10 + e11);
                lsum[rt][1] += (e02 + e03) + (e12 + e13);
                PH[rt][0] = f16x2(e00, e01);
                PH[rt][1] = f16x2(e02, e03);
                PH[rt][2] = f16x2(e10, e11);
                PH[rt][3] = f16x2(e12, e13);
            }

            const uint32_t vroff = (uint32_t)(np*16 + vrow_l)*128;
            #pragma unroll
            for (int dp = 0; dp < 4; dp++) {
                const uint32_t coff = ((uint32_t)dp*32 + vcol0) ^ kxor;
                uint32_t vh0, vh1, vh2, vh3;
                ldsm4t(vh0, vh1, vh2, vh3, cbase + 16384 + vroff + coff);
                #pragma unroll
                for (int rt = 0; rt < 2; rt++) {
                    mma_f16(O[rt][2*dp],   PH[rt], vh0, vh1);
                    mma_f16(O[rt][2*dp+1], PH[rt], vh2, vh3);
                }
            }
        }
    }

    // ---- rowsum reduce + store ----
    const int g  = lane >> 2;
    const int t2 = (lane & 3)*2;
    #pragma unroll
    for (int rt = 0; rt < 2; rt++) {
        lsum[rt][0] += __shfl_xor_sync(0xffffffffu, lsum[rt][0], 1);
        lsum[rt][0] += __shfl_xor_sync(0xffffffffu, lsum[rt][0], 2);
        lsum[rt][1] += __shfl_xor_sync(0xffffffffu, lsum[rt][1], 1);
        lsum[rt][1] += __shfl_xor_sync(0xffffffffu, lsum[rt][1], 2);
        const float inv0 = 1.0f / (8.0f * lsum[rt][0]);
        const float inv1 = 1.0f / (8.0f * lsum[rt][1]);
        const int row0 = qrow0 + 32*w + rt*16 + g;
        #pragma unroll
        for (int n = 0; n < 8; n++) {
            float2 r0 = {O[rt][n][0]*inv0, O[rt][n][1]*inv0};
            float2 r1 = {O[rt][n][2]*inv1, O[rt][n][3]*inv1};
            *(float2*)&out[(size_t)row0*64 + n*8 + t2]       = r0;
            *(float2*)&out[(size_t)(row0 + 8)*64 + n*8 + t2] = r1;
        }
    }
}

// =============================== launch =====================================
extern "C" void kernel_launch(void* const* d_in, const int* in_sizes, int n_in,
                              void* d_out, int out_size)
{
    const float* x    = (const float*)d_in[0];
    const float* ln_w = (const float*)d_in[1];
    const float* ln_b = (const float*)d_in[2];
    const float* Wq   = (const float*)d_in[3];
    const float* bq   = (const float*)d_in[4];
    const float* Wk   = (const float*)d_in[5];
    const float* bk   = (const float*)d_in[6];
    const float* Wv   = (const float*)d_in[7];
    const float* bv   = (const float*)d_in[8];
    float* out = (float*)d_out;

    cudaFuncSetAttribute(qkv_mma_kernel, cudaFuncAttributeMaxDynamicSharedMemorySize, QKV_SMEM);
    cudaFuncSetAttribute(attn_mma_kernel, cudaFuncAttributeMaxDynamicSharedMemorySize, AT_SMEM);

    w_split_kernel<<<(HD*HD + 255)/256, 256>>>(Wq, Wk, Wv);
    ln_split_kernel<<<(NB*SEQ)/8, 256>>>(x, ln_w, ln_b);
    qkv_mma_kernel<<<(BH*SEQ)/128, 256, QKV_SMEM>>>(bq, bk, bv);

    dim3 g2(SEQ/256, BH);
    attn_mma_kernel<<<g2, 256, AT_SMEM>>>(out);
}

// round 17
// speedup vs baseline: 1.0477x; 1.0477x over previous
#include <cuda_runtime.h>
#include <cuda_bf16.h>
#include <cuda_fp16.h>
#include <cstdint>

// Problem constants
#define NB   8
#define SEQ  1024
#define EMB  768
#define NH   12
#define HD   64
#define BH   (NB*NH)          // 96
#define NTOK (BH*SEQ*HD)      // 6291456
#define EXP_OFF 8.0f
#define EXP_CAP 11.0f         // exp arg clamp: keeps P < 60000 in fp16

// ---------------- fp16 split helpers ---------------------------------------
__device__ __forceinline__ void split2h(float2 f, uint32_t& hw, uint32_t& lw) {
    __half2 h = __float22half2_rn(f);
    float2 hf = __half22float2(h);
    __half2 l = __float22half2_rn(make_float2(f.x - hf.x, f.y - hf.y));
    hw = *(uint32_t*)&h;
    lw = *(uint32_t*)&l;
}

// ---------------- scratch (static device arrays; no allocation) -------------
__device__ __half g_qh[NTOK];                      // q,k,v: fp16 only
__device__ __half g_kh[NTOK];
__device__ __half g_vh[NTOK];
__device__ __half g_wqh[HD*HD], g_wql[HD*HD];      // W splits [n][e]
__device__ __half g_wkh[HD*HD], g_wkl[HD*HD];
__device__ __half g_wvh[HD*HD], g_wvl[HD*HD];

// ==================== Kernel 0: split weights to fp16 hi/lo =================
__global__ void w_split_kernel(const float* __restrict__ Wq,
                               const float* __restrict__ Wk,
                               const float* __restrict__ Wv)
{
    int i = blockIdx.x*256 + threadIdx.x;
    if (i < HD*HD) {
        float q = Wq[i], k = Wk[i], v = Wv[i];
        __half qh = __float2half_rn(q);
        __half kh = __float2half_rn(k);
        __half vh = __float2half_rn(v);
        g_wqh[i] = qh; g_wql[i] = __float2half_rn(q - __half2float(qh));
        g_wkh[i] = kh; g_wkl[i] = __float2half_rn(k - __half2float(kh));
        g_wvh[i] = vh; g_wvl[i] = __float2half_rn(v - __half2float(vh));
    }
}

// ---------------- MMA/ldsm/cp.async helpers ---------------------------------
__device__ __forceinline__ uint32_t smem_u32(const void* p) {
    uint32_t a;
    asm("{ .reg .u64 t; cvta.to.shared.u64 t, %1; cvt.u32.u64 %0, t; }"
        : "=r"(a) : "l"(p));
    return a;
}
__device__ __forceinline__ void ldsm4(uint32_t& r0, uint32_t& r1,
                                      uint32_t& r2, uint32_t& r3, uint32_t a) {
    asm volatile("ldmatrix.sync.aligned.m8n8.x4.shared.b16 {%0,%1,%2,%3}, [%4];"
                 : "=r"(r0), "=r"(r1), "=r"(r2), "=r"(r3) : "r"(a));
}
__device__ __forceinline__ void ldsm4t(uint32_t& r0, uint32_t& r1,
                                       uint32_t& r2, uint32_t& r3, uint32_t a) {
    asm volatile("ldmatrix.sync.aligned.m8n8.x4.trans.shared.b16 {%0,%1,%2,%3}, [%4];"
                 : "=r"(r0), "=r"(r1), "=r"(r2), "=r"(r3) : "r"(a));
}
__device__ __forceinline__ void mma_f16(float* c, const uint32_t* a,
                                        uint32_t b0, uint32_t b1) {
    asm volatile(
        "mma.sync.aligned.m16n8k16.row.col.f32.f16.f16.f32 "
        "{%0,%1,%2,%3}, {%4,%5,%6,%7}, {%8,%9}, {%0,%1,%2,%3};"
        : "+f"(c[0]), "+f"(c[1]), "+f"(c[2]), "+f"(c[3])
        : "r"(a[0]), "r"(a[1]), "r"(a[2]), "r"(a[3]), "r"(b0), "r"(b1));
}
__device__ __forceinline__ void cp16(uint32_t saddr, const void* g) {
    asm volatile("cp.async.cg.shared.global [%0], [%1], 16;"
                 :: "r"(saddr), "l"(g));
}
__device__ __forceinline__ uint32_t f16x2(float a, float b) {
    __half2 h = __float22half2_rn(make_float2(a, b));
    return *(uint32_t*)&h;
}

// ========== Kernel 1: fused LayerNorm + QKV projection (HMMA fp16x3) ========
// CTA = 128 chunks (8192 x-elements, spanning <=12 LN rows; chunks never
// cross rows since 768 = 12*64). LN stats + normalize+split in-kernel — no
// x_h/x_l global round trip.
#define QXH 0
#define QXL 16384
#define QW  32768        // 6 x 8KB weight arrays
#define QST 81920        // per-row mu/rs (12 + 12 floats)
#define QKV_SMEM 82048

__global__ void __launch_bounds__(256, 2)
qkv_mma_kernel(const float* __restrict__ x,
               const float* __restrict__ ln_w, const float* __restrict__ ln_b,
               const float* __restrict__ bq, const float* __restrict__ bk,
               const float* __restrict__ bv)
{
    extern __shared__ char smem[];
    const uint32_t sb = smem_u32(smem);
    float* s_mu = (float*)(smem + QST);
    float* s_rs = s_mu + 12;
    const int tid  = threadIdx.x;
    const int w    = tid >> 5;
    const int lane = tid & 31;
    const int m0   = blockIdx.x*128;

    // Phase 0: launch weight staging (overlaps LN below)
    for (int i = tid; i < 512; i += 256) {
        int row = i >> 3, seg = i & 7;
        uint32_t off = (uint32_t)row*128 + (((uint32_t)seg*16) ^ (((uint32_t)row & 7) << 4));
        size_t gb = (size_t)row*128 + seg*16;
        cp16(sb + QW           + off, (const char*)g_wqh + gb);
        cp16(sb + QW + 8192    + off, (const char*)g_wql + gb);
        cp16(sb + QW + 16384   + off, (const char*)g_wkh + gb);
        cp16(sb + QW + 24576   + off, (const char*)g_wkl + gb);
        cp16(sb + QW + 32768   + off, (const char*)g_wvh + gb);
        cp16(sb + QW + 40960   + off, (const char*)g_wvl + gb);
    }
    asm volatile("cp.async.commit_group;" ::: "memory");

    // Phase 1: LN stats for the <=12 covered x-rows (one warp per row)
    const int r0base = (m0*64)/EMB;
    const int nrows  = (m0*64 + 8191)/EMB - r0base + 1;
    for (int lr = w; lr < nrows; lr += 8) {
        const float* xr = &x[(size_t)(r0base + lr)*EMB + lane*24];
        float s = 0.f, s2 = 0.f;
        #pragma unroll
        for (int i = 0; i < 6; i++) {
            float4 t = *(const float4*)&xr[i*4];
            s  += (t.x + t.y) + (t.z + t.w);
            s2 += (t.x*t.x + t.y*t.y) + (t.z*t.z + t.w*t.w);
        }
        #pragma unroll
        for (int m = 16; m; m >>= 1) {
            s  += __shfl_xor_sync(0xffffffffu, s,  m);
            s2 += __shfl_xor_sync(0xffffffffu, s2, m);
        }
        if (lane == 0) {
            float mu  = s * (1.f/EMB);
            s_mu[lr] = mu;
            s_rs[lr] = rsqrtf(fmaf(-mu, mu, s2 * (1.f/EMB)) + 1e-5f);
        }
    }
    __syncthreads();   // stats ready

    // Phase 2: normalize + split + store to swizzled smem XH/XL
    #pragma unroll
    for (int it = 0; it < 4; it++) {
        const int j = (it*256 + tid)*8;     // 0..8191, 8 elems
        const int r = j >> 6, d = j & 63;
        const int mrow = m0 + r;
        const int xrow = mrow / 12;
        const int xcol = (mrow - xrow*12)*64 + d;
        const float mu = s_mu[xrow - r0base];
        const float rs = s_rs[xrow - r0base];
        const float* xp = &x[(size_t)xrow*EMB + xcol];
        float4 v0 = *(const float4*)xp;
        float4 v1 = *(const float4*)(xp + 4);
        float4 w0 = *(const float4*)&ln_w[xcol];
        float4 w1 = *(const float4*)&ln_w[xcol + 4];
        float4 b0 = *(const float4*)&ln_b[xcol];
        float4 b1 = *(const float4*)&ln_b[xcol + 4];
        uint32_t hw[4], lw[4];
        split2h(make_float2((v0.x-mu)*rs*w0.x+b0.x, (v0.y-mu)*rs*w0.y+b0.y), hw[0], lw[0]);
        split2h(make_float2((v0.z-mu)*rs*w0.z+b0.z, (v0.w-mu)*rs*w0.w+b0.w), hw[1], lw[1]);
        split2h(make_float2((v1.x-mu)*rs*w1.x+b1.x, (v1.y-mu)*rs*w1.y+b1.y), hw[2], lw[2]);
        split2h(make_float2((v1.z-mu)*rs*w1.z+b1.z, (v1.w-mu)*rs*w1.w+b1.w), hw[3], lw[3]);
        const uint32_t seg = (uint32_t)(d >> 3);
        const uint32_t off = (uint32_t)r*128 + ((seg*16) ^ (((uint32_t)r & 7) << 4));
        *(uint4*)(smem + QXH + off) = make_uint4(hw[0], hw[1], hw[2], hw[3]);
        *(uint4*)(smem + QXL + off) = make_uint4(lw[0], lw[1], lw[2], lw[3]);
    }
    asm volatile("cp.async.wait_group 0;" ::: "memory");
    __syncthreads();   // XH/XL + W all visible

    // Phase 3: three GEMMs (fp16 x3), write q,k,v fp16
    const int arow = 16*w + (lane & 7) + ((lane >> 3) & 1)*8;
    const uint32_t axor = ((uint32_t)arow & 7) << 4;
    const uint32_t abase = (uint32_t)arow*128;
    const uint32_t acol0 = ((uint32_t)(lane >> 4))*16;
    const int krow_l = (lane & 7) + ((lane >> 4) & 1)*8;
    const uint32_t kxor = ((uint32_t)lane & 7) << 4;
    const uint32_t kcol0 = ((uint32_t)((lane >> 3) & 1))*16;

    uint32_t XH[4][4], XL[4][4];
    #pragma unroll
    for (int kc = 0; kc < 4; kc++) {
        uint32_t a = sb + QXH + abase + (((uint32_t)kc*32 + acol0) ^ axor);
        ldsm4(XH[kc][0], XH[kc][1], XH[kc][2], XH[kc][3], a);
        uint32_t b = sb + QXL + abase + (((uint32_t)kc*32 + acol0) ^ axor);
        ldsm4(XL[kc][0], XL[kc][1], XL[kc][2], XL[kc][3], b);
    }

    const float* bias[3] = {bq, bk, bv};
    __half* outh[3] = {g_qh, g_kh, g_vh};

    const int g  = lane >> 2;
    const int t2 = (lane & 3)*2;
    const int r0 = m0 + 16*w + g;

    #pragma unroll
    for (int wt = 0; wt < 3; wt++) {
        const uint32_t wbh = sb + QW + (uint32_t)wt*16384;
        const uint32_t wbl = wbh + 8192;

        float C[8][4];
        #pragma unroll
        for (int n = 0; n < 8; n++)
            #pragma unroll
            for (int i = 0; i < 4; i++) C[n][i] = 0.f;

        #pragma unroll
        for (int np = 0; np < 4; np++) {
            const uint32_t roff = (uint32_t)(np*16 + krow_l)*128;
            #pragma unroll
            for (int kc = 0; kc < 4; kc++) {
                const uint32_t coff = ((uint32_t)kc*32 + kcol0) ^ kxor;
                uint32_t h0, h1, h2, h3, l0, l1, l2, l3;
                ldsm4(h0, h1, h2, h3, wbh + roff + coff);
                ldsm4(l0, l1, l2, l3, wbl + roff + coff);
                mma_f16(C[2*np],   XH[kc], h0, h1);
                mma_f16(C[2*np],   XH[kc], l0, l1);
                mma_f16(C[2*np],   XL[kc], h0, h1);
                mma_f16(C[2*np+1], XH[kc], h2, h3);
                mma_f16(C[2*np+1], XH[kc], l2, l3);
                mma_f16(C[2*np+1], XL[kc], h2, h3);
            }
        }

        #pragma unroll
        for (int nt = 0; nt < 8; nt++) {
            const int col = nt*8 + t2;
            const float2 bb = *(const float2*)&bias[wt][col];
            uint32_t p0 = f16x2(C[nt][0] + bb.x, C[nt][1] + bb.y);
            uint32_t p1 = f16x2(C[nt][2] + bb.x, C[nt][3] + bb.y);
            *(uint32_t*)((char*)outh[wt] + ((size_t)r0*64 + col)*2)     = p0;
            *(uint32_t*)((char*)outh[wt] + ((size_t)(r0+8)*64 + col)*2) = p1;
        }
    }
}

// =============== Kernel 2: warp-MMA (HMMA fp16) flash attention =============
// (R15 config: 128-row q-tile, M=16/warp, 2 CTAs/SM, 128-key stages)
__device__ __forceinline__ float expc(float s) {
    return __expf(fminf(s - EXP_OFF, EXP_CAP));
}

#define AQH 0
#define ASTG 16384
#define STG_SZ 32768        // KH(16K) + VH(16K) per 128-key stage
#define AT_SMEM 81920

__global__ void __launch_bounds__(256, 2)
attn_mma_kernel(float* __restrict__ out)
{
    extern __shared__ char smem[];
    const uint32_t sb = smem_u32(smem);
    const int tid  = threadIdx.x;
    const int w    = tid >> 5;
    const int lane = tid & 31;
    const int bh   = blockIdx.y;
    const int qrow0 = bh*SEQ + blockIdx.x*128;
    const int krowb = bh*SEQ;

    // ---- stage Q ----
    for (int i = tid; i < 1024; i += 256) {
        int row = i >> 3, seg = i & 7;
        uint32_t off = (uint32_t)row*128 + (((uint32_t)seg*16) ^ (((uint32_t)row & 7) << 4));
        *(uint4*)(smem + AQH + off) = *(const uint4*)((const char*)g_qh + (size_t)(qrow0 + row)*128 + seg*16);
    }

    // ---- prologue prefetch: k-tile 0 (128 keys: KH+VH) into stage 0 ----
    {
        const uint32_t base = sb + ASTG;
        for (int i = tid; i < 1024; i += 256) {
            int row = i >> 3, seg = i & 7;
            uint32_t off = (uint32_t)row*128 + (((uint32_t)seg*16) ^ (((uint32_t)row & 7) << 4));
            size_t gb = (size_t)(krowb + row)*128 + seg*16;
            cp16(base + off,         (const char*)g_kh + gb);
            cp16(base + 16384 + off, (const char*)g_vh + gb);
        }
        asm volatile("cp.async.commit_group;" ::: "memory");
    }
    __syncthreads();

    const int arow = 16*w + (lane & 7) + ((lane >> 3) & 1)*8;
    const uint32_t axor = ((uint32_t)arow & 7) << 4;
    const uint32_t abase = (uint32_t)arow*128;
    const uint32_t acol0 = ((uint32_t)(lane >> 4))*16;
    const int krow_l = (lane & 7) + ((lane >> 4) & 1)*8;
    const uint32_t kxor = ((uint32_t)lane & 7) << 4;
    const uint32_t kcol0 = ((uint32_t)((lane >> 3) & 1))*16;
    const int vrow_l = (lane & 7) + ((lane >> 3) & 1)*8;
    const uint32_t vcol0 = ((uint32_t)((lane >> 4) & 1))*16;

    uint32_t QH[4][4];
    #pragma unroll
    for (int kc = 0; kc < 4; kc++) {
        uint32_t a = sb + AQH + abase + (((uint32_t)kc*32 + acol0) ^ axor);
        ldsm4(QH[kc][0], QH[kc][1], QH[kc][2], QH[kc][3], a);
    }

    float O[8][4];
    #pragma unroll
    for (int n = 0; n < 8; n++)
        #pragma unroll
        for (int i = 0; i < 4; i++) O[n][i] = 0.f;
    float lsum0 = 0.f, lsum1 = 0.f;

    for (int kt = 0; kt < 8; kt++) {
        const uint32_t cbase = sb + ASTG + (uint32_t)(kt & 1)*STG_SZ;

        asm volatile("cp.async.wait_group 0;" ::: "memory");
        __syncthreads();   // stage kt visible; all warps done with other stage

        if (kt + 1 < 8) {
            const int krow0 = krowb + (kt + 1)*128;
            const uint32_t pbase = sb + ASTG + (uint32_t)((kt + 1) & 1)*STG_SZ;
            for (int i = tid; i < 1024; i += 256) {
                int row = i >> 3, seg = i & 7;
                uint32_t off = (uint32_t)row*128 + (((uint32_t)seg*16) ^ (((uint32_t)row & 7) << 4));
                size_t gb = (size_t)(krow0 + row)*128 + seg*16;
                cp16(pbase + off,         (const char*)g_kh + gb);
                cp16(pbase + 16384 + off, (const char*)g_vh + gb);
            }
            asm volatile("cp.async.commit_group;" ::: "memory");
        }

        // ---- per-strip pipeline: S(np) -> exp -> PV(np), 8 strips of 16 keys
        #pragma unroll
        for (int np = 0; np < 8; np++) {
            float SH[2][4];
            #pragma unroll
            for (int n = 0; n < 2; n++)
                #pragma unroll
                for (int i = 0; i < 4; i++) SH[n][i] = 0.f;

            const uint32_t kroff = (uint32_t)(np*16 + krow_l)*128;
            #pragma unroll
            for (int kc = 0; kc < 4; kc++) {
                const uint32_t coff = ((uint32_t)kc*32 + kcol0) ^ kxor;
                uint32_t bh0, bh1, bh2, bh3;
                ldsm4(bh0, bh1, bh2, bh3, cbase + kroff + coff);
                mma_f16(SH[0], QH[kc], bh0, bh1);
                mma_f16(SH[1], QH[kc], bh2, bh3);
            }

            float e00 = expc(SH[0][0]);
            float e01 = expc(SH[0][1]);
            float e02 = expc(SH[0][2]);
            float e03 = expc(SH[0][3]);
            float e10 = expc(SH[1][0]);
            float e11 = expc(SH[1][1]);
            float e12 = expc(SH[1][2]);
            float e13 = expc(SH[1][3]);
            lsum0 += (e00 + e01) + (e10 + e11);
            lsum1 += (e02 + e03) + (e12 + e13);

            uint32_t PH[4];
            PH[0] = f16x2(e00, e01);
            PH[1] = f16x2(e02, e03);
            PH[2] = f16x2(e10, e11);
            PH[3] = f16x2(e12, e13);

            const uint32_t vroff = (uint32_t)(np*16 + vrow_l)*128;
            #pragma unroll
            for (int dp = 0; dp < 4; dp++) {
                const uint32_t coff = ((uint32_t)dp*32 + vcol0) ^ kxor;
                uint32_t vh0, vh1, vh2, vh3;
                ldsm4t(vh0, vh1, vh2, vh3, cbase + 16384 + vroff + coff);
                mma_f16(O[2*dp],   PH, vh0, vh1);
                mma_f16(O[2*dp+1], PH, vh2, vh3);
            }
        }
    }

    lsum0 += __shfl_xor_sync(0xffffffffu, lsum0, 1);
    lsum0 += __shfl_xor_sync(0xffffffffu, lsum0, 2);
    lsum1 += __shfl_xor_sync(0xffffffffu, lsum1, 1);
    lsum1 += __shfl_xor_sync(0xffffffffu, lsum1, 2);
    const float inv0 = 1.0f / (8.0f * lsum0);
    const float inv1 = 1.0f / (8.0f * lsum1);

    const int g  = lane >> 2;
    const int t2 = (lane & 3)*2;
    const int row0 = qrow0 + 16*w + g;
    #pragma unroll
    for (int n = 0; n < 8; n++) {
        float2 r0 = {O[n][0]*inv0, O[n][1]*inv0};
        float2 r1 = {O[n][2]*inv1, O[n][3]*inv1};
        *(float2*)&out[(size_t)row0*64 + n*8 + t2]       = r0;
        *(float2*)&out[(size_t)(row0 + 8)*64 + n*8 + t2] = r1;
    }
}

// =============================== launch =====================================
extern "C" void kernel_launch(void* const* d_in, const int* in_sizes, int n_in,
                              void* d_out, int out_size)
{
    const float* x    = (const float*)d_in[0];
    const float* ln_w = (const float*)d_in[1];
    const float* ln_b = (const float*)d_in[2];
    const float* Wq   = (const float*)d_in[3];
    const float* bq   = (const float*)d_in[4];
    const float* Wk   = (const float*)d_in[5];
    const float* bk   = (const float*)d_in[6];
    const float* Wv   = (const float*)d_in[7];
    const float* bv   = (const float*)d_in[8];
    float* out = (float*)d_out;

    cudaFuncSetAttribute(qkv_mma_kernel, cudaFuncAttributeMaxDynamicSharedMemorySize, QKV_SMEM);
    cudaFuncSetAttribute(attn_mma_kernel, cudaFuncAttributeMaxDynamicSharedMemorySize, AT_SMEM);

    w_split_kernel<<<(HD*HD + 255)/256, 256>>>(Wq, Wk, Wv);
    qkv_mma_kernel<<<(BH*SEQ)/128, 256, QKV_SMEM>>>(x, ln_w, ln_b, bq, bk, bv);

    dim3 g2(SEQ/128, BH);
    attn_mma_kernel<<<g2, 256, AT_SMEM>>>(out);
}